// round 15
// baseline (speedup 1.0000x reference)
#include <cuda_runtime.h>
#include <stdint.h>

#define BB 4
#define QQ 256
#define MMM 256
#define HH 512
#define DQS 512
#define DKS 512
#define DC (DQS + DKS)

// Scratch device globals
__device__ float g_qproj[BB * QQ * HH];    // 2 MB
__device__ float g_kproj[BB * MMM * HH];   // 2 MB
__device__ float g_logits[BB * QQ * MMM];  // 1 MB (raw logits; k3 masks)
__device__ float g_partial[BB * QQ * DQS]; // 2 MB  query @ Wo1^T + bo
__device__ float g_P2[BB * MMM * DQS];     // 2 MB  memory @ Wo2^T

// ---------------------------------------------------------------------------
// helpers
// ---------------------------------------------------------------------------
__device__ __forceinline__ float f2tf32(float x) {
    uint32_t r;
    asm("cvt.rna.tf32.f32 %0, %1;" : "=r"(r) : "f"(x));
    return __uint_as_float(r);
}
__device__ __forceinline__ uint32_t fu(float x) { return __float_as_uint(x); }

__device__ __forceinline__ void mma_tf32(float c[4], const uint32_t a[4],
                                         const uint32_t b[2]) {
    asm volatile(
        "mma.sync.aligned.m16n8k8.row.col.f32.tf32.tf32.f32 "
        "{%0,%1,%2,%3}, {%4,%5,%6,%7}, {%8,%9}, {%0,%1,%2,%3};"
        : "+f"(c[0]), "+f"(c[1]), "+f"(c[2]), "+f"(c[3])
        : "r"(a[0]), "r"(a[1]), "r"(a[2]), "r"(a[3]), "r"(b[0]), "r"(b[1]));
}

// ---------------------------------------------------------------------------
// NT tf32 GEMM body, 256 threads, 32x64 tile, BK=32, single smem buffer,
// register prefetch, cvt at store. 8 warps in 2x4, warp tile 16x16.
// High-occupancy variant: acc = 8 regs/thread, smem 13.8 KB.
// ---------------------------------------------------------------------------
template<bool BIAS>
__device__ __forceinline__ void gemm_nt_32x64(
    float (*As)[36], float (*Ws)[36],
    int row0, int col0,
    const float* __restrict__ A, int lda,
    const float* __restrict__ W, int ldw,
    const float* __restrict__ bias,
    float* __restrict__ C, int ldc, int K)
{
    const int tid  = threadIdx.x;
    const int lane = tid & 31;
    const int g    = lane >> 2;
    const int tg   = lane & 3;
    const int w    = tid >> 5;
    const int wm   = (w >> 2) << 4;   // 0 or 16
    const int wn   = (w & 3) << 4;    // 0,16,32,48

    // loaders: A 32 rows x 8 f4 = 256 (1/thread); W 64 rows x 8 f4 = 512 (2/thread)
    const int ar = tid >> 3, ac = (tid & 7) << 2;
    int wr[2], wc[2];
#pragma unroll
    for (int c = 0; c < 2; c++) {
        int idx = tid + (c << 8);
        wr[c] = idx >> 3;
        wc[c] = (idx & 7) << 2;
    }

    float acc[2][4];
#pragma unroll
    for (int ni = 0; ni < 2; ni++)
#pragma unroll
        for (int j = 0; j < 4; j++) acc[ni][j] = 0.f;

    float4 pa, pw[2];
    pa = *reinterpret_cast<const float4*>(A + (size_t)(row0 + ar) * lda + ac);
#pragma unroll
    for (int c = 0; c < 2; c++)
        pw[c] = *reinterpret_cast<const float4*>(W + (size_t)(col0 + wr[c]) * ldw + wc[c]);

    for (int k0 = 0; k0 < K; k0 += 32) {
        {
            float4 va = pa;
            *reinterpret_cast<float4*>(&As[ar][ac]) =
                make_float4(f2tf32(va.x), f2tf32(va.y), f2tf32(va.z), f2tf32(va.w));
        }
#pragma unroll
        for (int c = 0; c < 2; c++) {
            float4 vw = pw[c];
            *reinterpret_cast<float4*>(&Ws[wr[c]][wc[c]]) =
                make_float4(f2tf32(vw.x), f2tf32(vw.y), f2tf32(vw.z), f2tf32(vw.w));
        }
        __syncthreads();

        int kn = k0 + 32;
        if (kn < K) {
            pa = *reinterpret_cast<const float4*>(A + (size_t)(row0 + ar) * lda + kn + ac);
#pragma unroll
            for (int c = 0; c < 2; c++)
                pw[c] = *reinterpret_cast<const float4*>(
                    W + (size_t)(col0 + wr[c]) * ldw + kn + wc[c]);
        }

#pragma unroll
        for (int ks = 0; ks < 4; ks++) {
            const int kk = ks << 3;
            uint32_t af[4], bf[2][2];
            {
                int r = wm + g;
                af[0] = fu(As[r][kk + tg]);
                af[1] = fu(As[r + 8][kk + tg]);
                af[2] = fu(As[r][kk + tg + 4]);
                af[3] = fu(As[r + 8][kk + tg + 4]);
            }
#pragma unroll
            for (int ni = 0; ni < 2; ni++) {
                int cn = wn + (ni << 3) + g;
                bf[ni][0] = fu(Ws[cn][kk + tg]);
                bf[ni][1] = fu(Ws[cn][kk + tg + 4]);
            }
#pragma unroll
            for (int ni = 0; ni < 2; ni++)
                mma_tf32(acc[ni], af, bf[ni]);
        }
        __syncthreads();
    }

#pragma unroll
    for (int ni = 0; ni < 2; ni++) {
        int col = col0 + wn + (ni << 3) + (tg << 1);
        float b0 = 0.f, b1 = 0.f;
        if (BIAS) { b0 = bias[col]; b1 = bias[col + 1]; }
        int r0 = row0 + wm + g;
        int r1 = r0 + 8;
        *reinterpret_cast<float2*>(C + (size_t)r0 * ldc + col) =
            make_float2(acc[ni][0] + b0, acc[ni][1] + b1);
        *reinterpret_cast<float2*>(C + (size_t)r1 * ldc + col) =
            make_float2(acc[ni][2] + b0, acc[ni][3] + b1);
    }
}

// ---------------------------------------------------------------------------
// K1: qproj + kproj. 512 blocks x 256 thr, 32x64 tiles (high occupancy).
// ---------------------------------------------------------------------------
__global__ void __launch_bounds__(256) k1_proj(
    const float* __restrict__ query, const float* __restrict__ memory,
    const float* __restrict__ Wq, const float* __restrict__ bq,
    const float* __restrict__ Wk, const float* __restrict__ bk)
{
    __shared__ float As[32][36];
    __shared__ float Ws[64][36];
    const int t = blockIdx.x & 255;          // 32 row-tiles x 8 col-tiles
    const int row0 = (t >> 3) << 5;
    const int col0 = (t & 7) << 6;
    if (blockIdx.x < 256)
        gemm_nt_32x64<true>(As, Ws, row0, col0, query, DQS, Wq, DQS, bq,
                            g_qproj, HH, DQS);
    else
        gemm_nt_32x64<true>(As, Ws, row0, col0, memory, DKS, Wk, DKS, bk,
                            g_kproj, HH, DKS);
}

// ---------------------------------------------------------------------------
// NT tf32 GEMM body 64x64 (round-6 exact) — used only by k2's fused blocks.
// ---------------------------------------------------------------------------
template<bool BIAS>
__device__ __forceinline__ void gemm_nt_256(
    float (*As)[36], float (*Ws)[36],
    int row0, int col0,
    const float* __restrict__ A, int lda,
    const float* __restrict__ W, int ldw,
    const float* __restrict__ bias,
    float* __restrict__ C, int ldc, int K)
{
    const int tid  = threadIdx.x;
    const int lane = tid & 31;
    const int g    = lane >> 2;
    const int tg   = lane & 3;
    const int w    = tid >> 5;
    const int wm   = (w >> 2) << 5;
    const int wn   = (w & 3) << 4;

    int lr[2], lc[2];
#pragma unroll
    for (int c = 0; c < 2; c++) {
        int idx = tid + (c << 8);
        lr[c] = idx >> 3;
        lc[c] = (idx & 7) << 2;
    }

    float acc[2][2][4];
#pragma unroll
    for (int mi = 0; mi < 2; mi++)
#pragma unroll
        for (int ni = 0; ni < 2; ni++)
#pragma unroll
            for (int j = 0; j < 4; j++) acc[mi][ni][j] = 0.f;

    float4 pa[2], pw[2];
#pragma unroll
    for (int c = 0; c < 2; c++) {
        pa[c] = *reinterpret_cast<const float4*>(A + (size_t)(row0 + lr[c]) * lda + lc[c]);
        pw[c] = *reinterpret_cast<const float4*>(W + (size_t)(col0 + lr[c]) * ldw + lc[c]);
    }

    for (int k0 = 0; k0 < K; k0 += 32) {
#pragma unroll
        for (int c = 0; c < 2; c++) {
            float4 va = pa[c], vw = pw[c];
            *reinterpret_cast<float4*>(&As[lr[c]][lc[c]]) =
                make_float4(f2tf32(va.x), f2tf32(va.y), f2tf32(va.z), f2tf32(va.w));
            *reinterpret_cast<float4*>(&Ws[lr[c]][lc[c]]) =
                make_float4(f2tf32(vw.x), f2tf32(vw.y), f2tf32(vw.z), f2tf32(vw.w));
        }
        __syncthreads();

        int kn = k0 + 32;
        if (kn < K) {
#pragma unroll
            for (int c = 0; c < 2; c++) {
                pa[c] = *reinterpret_cast<const float4*>(
                    A + (size_t)(row0 + lr[c]) * lda + kn + lc[c]);
                pw[c] = *reinterpret_cast<const float4*>(
                    W + (size_t)(col0 + lr[c]) * ldw + kn + lc[c]);
            }
        }

#pragma unroll
        for (int ks = 0; ks < 4; ks++) {
            const int kk = ks << 3;
            uint32_t af[2][4], bf[2][2];
#pragma unroll
            for (int mi = 0; mi < 2; mi++) {
                int r = wm + (mi << 4) + g;
                af[mi][0] = fu(As[r][kk + tg]);
                af[mi][1] = fu(As[r + 8][kk + tg]);
                af[mi][2] = fu(As[r][kk + tg + 4]);
                af[mi][3] = fu(As[r + 8][kk + tg + 4]);
            }
#pragma unroll
            for (int ni = 0; ni < 2; ni++) {
                int cn = wn + (ni << 3) + g;
                bf[ni][0] = fu(Ws[cn][kk + tg]);
                bf[ni][1] = fu(Ws[cn][kk + tg + 4]);
            }
#pragma unroll
            for (int mi = 0; mi < 2; mi++)
#pragma unroll
                for (int ni = 0; ni < 2; ni++)
                    mma_tf32(acc[mi][ni], af[mi], bf[ni]);
        }
        __syncthreads();
    }

#pragma unroll
    for (int mi = 0; mi < 2; mi++) {
#pragma unroll
        for (int ni = 0; ni < 2; ni++) {
            int col = col0 + wn + (ni << 3) + (tg << 1);
            float b0 = 0.f, b1 = 0.f;
            if (BIAS) { b0 = bias[col]; b1 = bias[col + 1]; }
            int r0 = row0 + wm + (mi << 4) + g;
            int r1 = r0 + 8;
            *reinterpret_cast<float2*>(C + (size_t)r0 * ldc + col) =
                make_float2(acc[mi][ni][0] + b0, acc[mi][ni][1] + b1);
            *reinterpret_cast<float2*>(C + (size_t)r1 * ldc + col) =
                make_float2(acc[mi][ni][2] + b0, acc[mi][ni][3] + b1);
        }
    }
}

// ---------------------------------------------------------------------------
// Scores body (round-6 exact: f32 tanh.approx, raw logits; k3 masks).
// ---------------------------------------------------------------------------
__device__ __forceinline__ void scores_body(int bid, float (*ks)[512],
                                            const float* __restrict__ Wl)
{
    const int b  = bid >> 7;
    const int qg = (bid >> 2) & 31;
    const int mg = bid & 3;
    const int q0 = qg << 3;
    const int m0base = mg << 6;

    const int tid = threadIdx.x;
    const int lane = tid & 31;
    const int w = tid >> 5;
    const int q = q0 + w;

    float qr[16], wl[16];
    const float* qp = g_qproj + ((size_t)(b * QQ + q)) * HH;
#pragma unroll
    for (int j = 0; j < 16; j++) {
        qr[j] = qp[lane + 32 * j];
        wl[j] = Wl[lane + 32 * j];
    }

    float* lout = g_logits + ((size_t)(b * QQ + q)) * MMM;

    for (int t = 0; t < 4; t++) {
        const int m0 = m0base + (t << 4);
        __syncthreads();
        const float* kp = g_kproj + ((size_t)(b * MMM + m0)) * HH;
#pragma unroll
        for (int i = 0; i < 8; i++) {
            int idx = tid + (i << 8);
            int mm = idx >> 7;
            int c4 = (idx & 127) << 2;
            *reinterpret_cast<float4*>(&ks[mm][c4]) =
                *reinterpret_cast<const float4*>(kp + mm * HH + c4);
        }
        __syncthreads();

#pragma unroll 4
        for (int mm = 0; mm < 16; mm++) {
            float acc = 0.f;
#pragma unroll
            for (int j = 0; j < 16; j++) {
                float s = qr[j] + ks[mm][lane + 32 * j];
                float th;
                asm("tanh.approx.f32 %0, %1;" : "=f"(th) : "f"(s));
                acc = fmaf(wl[j], th, acc);
            }
#pragma unroll
            for (int o = 16; o > 0; o >>= 1)
                acc += __shfl_xor_sync(0xFFFFFFFFu, acc, o);
            if (lane == 0) lout[m0 + mm] = acc;
        }
    }
}

// ---------------------------------------------------------------------------
// K2: scores (512) + partial=query@Wo1^T+bo (128) + P2=memory@Wo2^T (128).
// (round-6 exact)
// ---------------------------------------------------------------------------
__global__ void __launch_bounds__(256) k2_scores_fused(
    const float* __restrict__ query, const float* __restrict__ memory,
    const float* __restrict__ Wo, const float* __restrict__ bo,
    const float* __restrict__ Wl)
{
    __shared__ __align__(16) union {
        float ks[16][512];                                 // 32 KB
        struct { float As[64][36]; float Ws[64][36]; } g;  // 18 KB
    } sm;

    const int bid = blockIdx.x;
    if (bid < 512) {
        scores_body(bid, sm.ks, Wl);
    } else if (bid < 640) {
        const int t = bid - 512;
        gemm_nt_256<true>(sm.g.As, sm.g.Ws, (t >> 3) << 6, (t & 7) << 6,
                          query, DQS, Wo, DC, bo, g_partial, DQS, DQS);
    } else {
        const int t = bid - 640;
        gemm_nt_256<false>(sm.g.As, sm.g.Ws, (t >> 3) << 6, (t & 7) << 6,
                           memory, DKS, Wo + DQS, DC, nullptr, g_P2, DQS, DKS);
    }
}

// ---------------------------------------------------------------------------
// K3: softmax + mask (round-6 exact). 256 blocks x 128 threads.
// ---------------------------------------------------------------------------
__global__ void __launch_bounds__(128) k3_softmax(
    const unsigned int* __restrict__ mask,
    float* __restrict__ weights)
{
    const int bid = blockIdx.x;
    const int b = bid >> 6;
    const int lane = threadIdx.x & 31;
    const int w = threadIdx.x >> 5;
    const int q = ((bid & 63) << 2) + w;

    const float* lin = g_logits + ((size_t)(b * QQ + q)) * MMM;
    const unsigned int* mrow = mask + b * MMM;

    float v[8];
    float mx = -3.4e38f;
#pragma unroll
    for (int j = 0; j < 8; j++) {
        int m = lane + 32 * j;
        float s = lin[m];
        if (mrow[m] != 0u) s = -1e18f;
        v[j] = s;
        mx = fmaxf(mx, s);
    }
#pragma unroll
    for (int o = 16; o > 0; o >>= 1)
        mx = fmaxf(mx, __shfl_xor_sync(0xFFFFFFFFu, mx, o));
    float sum = 0.f;
#pragma unroll
    for (int j = 0; j < 8; j++) {
        v[j] = __expf(v[j] - mx);
        sum += v[j];
    }
#pragma unroll
    for (int o = 16; o > 0; o >>= 1)
        sum += __shfl_xor_sync(0xFFFFFFFFu, sum, o);
    float inv = 1.f / sum;

    float* wout = weights + ((size_t)(b * QQ + q)) * MMM;
#pragma unroll
    for (int j = 0; j < 8; j++)
        wout[lane + 32 * j] = v[j] * inv;
}

// ---------------------------------------------------------------------------
// K4: out = tanh(partial + weights @ P2)  (batched NN, K = 256).
// 32x64 tiles, 256 threads (warp tile 16x16), grid 256 blocks.
// High-occupancy: ~14 warps/SM vs 6.9 in the 64x64/256thr variant.
// ---------------------------------------------------------------------------
__global__ void __launch_bounds__(256) k4_final(
    const float* __restrict__ Wt, float* __restrict__ out)
{
    const int bid = blockIdx.x;
    const int b  = bid >> 6;
    const int t  = bid & 63;
    const int row0 = (t >> 3) << 5;   // 32-row q tile
    const int col0 = (t & 7) << 6;    // 64-col o tile

    const float* A  = Wt   + (size_t)b * QQ * MMM;   // weights, lda = MMM
    const float* Bm = g_P2 + (size_t)b * MMM * DQS;  // P2, ldb = DQS

    __shared__ float As[32][36];
    __shared__ float Bs[32][72];

    const int tid  = threadIdx.x;
    const int lane = tid & 31;
    const int g    = lane >> 2;
    const int tg   = lane & 3;
    const int w    = tid >> 5;
    const int wm   = (w >> 2) << 4;   // 0 or 16
    const int wn   = (w & 3) << 4;    // 0,16,32,48

    // loaders: A 32x8 f4 = 256 (1/thread); B 32x16 f4 = 512 (2/thread)
    const int ar = tid >> 3, ac = (tid & 7) << 2;
    int br[2], bc[2];
#pragma unroll
    for (int c = 0; c < 2; c++) {
        int idx = tid + (c << 8);
        br[c] = idx >> 4;
        bc[c] = (idx & 15) << 2;
    }

    float acc[2][4];
#pragma unroll
    for (int ni = 0; ni < 2; ni++)
#pragma unroll
        for (int j = 0; j < 4; j++) acc[ni][j] = 0.f;

    float4 pa, pb[2];
    pa = *reinterpret_cast<const float4*>(A + (size_t)(row0 + ar) * MMM + ac);
#pragma unroll
    for (int c = 0; c < 2; c++)
        pb[c] = *reinterpret_cast<const float4*>(Bm + (size_t)br[c] * DQS + col0 + bc[c]);

    for (int k0 = 0; k0 < MMM; k0 += 32) {
        {
            float4 va = pa;
            *reinterpret_cast<float4*>(&As[ar][ac]) =
                make_float4(f2tf32(va.x), f2tf32(va.y), f2tf32(va.z), f2tf32(va.w));
        }
#pragma unroll
        for (int c = 0; c < 2; c++) {
            float4 vb = pb[c];
            *reinterpret_cast<float4*>(&Bs[br[c]][bc[c]]) =
                make_float4(f2tf32(vb.x), f2tf32(vb.y), f2tf32(vb.z), f2tf32(vb.w));
        }
        __syncthreads();

        int kn = k0 + 32;
        if (kn < MMM) {
            pa = *reinterpret_cast<const float4*>(A + (size_t)(row0 + ar) * MMM + kn + ac);
#pragma unroll
            for (int c = 0; c < 2; c++)
                pb[c] = *reinterpret_cast<const float4*>(
                    Bm + (size_t)(kn + br[c]) * DQS + col0 + bc[c]);
        }

#pragma unroll
        for (int ks = 0; ks < 4; ks++) {
            const int kk = ks << 3;
            uint32_t af[4], bf[2][2];
            {
                int r = wm + g;
                af[0] = fu(As[r][kk + tg]);
                af[1] = fu(As[r + 8][kk + tg]);
                af[2] = fu(As[r][kk + tg + 4]);
                af[3] = fu(As[r + 8][kk + tg + 4]);
            }
#pragma unroll
            for (int ni = 0; ni < 2; ni++) {
                int cn = wn + (ni << 3) + g;
                bf[ni][0] = fu(Bs[kk + tg][cn]);
                bf[ni][1] = fu(Bs[kk + tg + 4][cn]);
            }
#pragma unroll
            for (int ni = 0; ni < 2; ni++)
                mma_tf32(acc[ni], af, bf[ni]);
        }
        __syncthreads();
    }

#pragma unroll
    for (int ni = 0; ni < 2; ni++) {
        int col = col0 + wn + (ni << 3) + (tg << 1);
        size_t r0 = (size_t)b * QQ + row0 + wm + g;
        size_t r1 = r0 + 8;
        float2 p0 = *reinterpret_cast<const float2*>(&g_partial[r0 * DQS + col]);
        float2 p1 = *reinterpret_cast<const float2*>(&g_partial[r1 * DQS + col]);
        *reinterpret_cast<float2*>(out + r0 * DQS + col) =
            make_float2(tanhf(acc[ni][0] + p0.x), tanhf(acc[ni][1] + p0.y));
        *reinterpret_cast<float2*>(out + r1 * DQS + col) =
            make_float2(tanhf(acc[ni][2] + p1.x), tanhf(acc[ni][3] + p1.y));
    }
}

// ---------------------------------------------------------------------------
// Launch
// ---------------------------------------------------------------------------
extern "C" void kernel_launch(void* const* d_in, const int* in_sizes, int n_in,
                              void* d_out, int out_size)
{
    const float* query  = (const float*)d_in[0];
    const float* memory = (const float*)d_in[1];
    const unsigned int* mask = (const unsigned int*)d_in[2];
    const float* Wk = (const float*)d_in[3];
    const float* bk = (const float*)d_in[4];
    const float* Wq = (const float*)d_in[5];
    const float* bq = (const float*)d_in[6];
    const float* Wl = (const float*)d_in[7];
    // d_in[8] = bl (uniform shift — cancels in softmax)
    const float* Wo = (const float*)d_in[9];
    const float* bo = (const float*)d_in[10];

    float* out     = (float*)d_out;
    float* weights = out + BB * QQ * DQS;

    k1_proj<<<512, 256>>>(query, memory, Wq, bq, Wk, bk);
    k2_scores_fused<<<768, 256>>>(query, memory, Wo, bo, Wl);
    k3_softmax<<<256, 128>>>(mask, weights);
    k4_final<<<256, 256>>>(weights, out);
}

// round 17
// speedup vs baseline: 1.0517x; 1.0517x over previous
#include <cuda_runtime.h>
#include <stdint.h>

#define BB 4
#define QQ 256
#define MMM 256
#define HH 512
#define DQS 512
#define DKS 512
#define DC (DQS + DKS)

// Scratch device globals
__device__ float g_qproj[BB * QQ * HH];    // 2 MB
__device__ float g_kproj[BB * MMM * HH];   // 2 MB
__device__ float g_logits[BB * QQ * MMM];  // 1 MB (raw logits; k3 masks)
__device__ float g_partial[BB * QQ * DQS]; // 2 MB  query @ Wo1^T + bo
__device__ float g_P2[BB * MMM * DQS];     // 2 MB  memory @ Wo2^T

// ---------------------------------------------------------------------------
// helpers
// ---------------------------------------------------------------------------
__device__ __forceinline__ float f2tf32(float x) {
    uint32_t r;
    asm("cvt.rna.tf32.f32 %0, %1;" : "=r"(r) : "f"(x));
    return __uint_as_float(r);
}
__device__ __forceinline__ uint32_t fu(float x) { return __float_as_uint(x); }

__device__ __forceinline__ void mma_tf32(float c[4], const uint32_t a[4],
                                         const uint32_t b[2]) {
    asm volatile(
        "mma.sync.aligned.m16n8k8.row.col.f32.tf32.tf32.f32 "
        "{%0,%1,%2,%3}, {%4,%5,%6,%7}, {%8,%9}, {%0,%1,%2,%3};"
        : "+f"(c[0]), "+f"(c[1]), "+f"(c[2]), "+f"(c[3])
        : "r"(a[0]), "r"(a[1]), "r"(a[2]), "r"(a[3]), "r"(b[0]), "r"(b[1]));
}

// ---------------------------------------------------------------------------
// K1 GEMM body: 64x64 tile, BK=64 (8 K-iters for K=512), 256 threads.
// 8 warps (2x4), warp tile 32x16. Smem stride 68 -> conflict-free
// fragment LDS (bank = 4r + c pattern, all 32 distinct per access).
// Register prefetch, cvt at store, single buffer.
// ---------------------------------------------------------------------------
template<bool BIAS>
__device__ __forceinline__ void gemm_nt_bk64(
    float (*As)[68], float (*Ws)[68],
    int row0, int col0,
    const float* __restrict__ A, int lda,
    const float* __restrict__ W, int ldw,
    const float* __restrict__ bias,
    float* __restrict__ C, int ldc, int K)
{
    const int tid  = threadIdx.x;
    const int lane = tid & 31;
    const int g    = lane >> 2;
    const int tg   = lane & 3;
    const int w    = tid >> 5;
    const int wm   = (w >> 2) << 5;
    const int wn   = (w & 3) << 4;

    // loaders: 64 rows x 16 f4 = 1024 f4 per tile, 4 per thread (A and W each)
    int lr[4], lc[4];
#pragma unroll
    for (int c = 0; c < 4; c++) {
        int idx = tid + (c << 8);
        lr[c] = idx >> 4;
        lc[c] = (idx & 15) << 2;
    }

    float acc[2][2][4];
#pragma unroll
    for (int mi = 0; mi < 2; mi++)
#pragma unroll
        for (int ni = 0; ni < 2; ni++)
#pragma unroll
            for (int j = 0; j < 4; j++) acc[mi][ni][j] = 0.f;

    float4 pa[4], pw[4];
#pragma unroll
    for (int c = 0; c < 4; c++) {
        pa[c] = *reinterpret_cast<const float4*>(A + (size_t)(row0 + lr[c]) * lda + lc[c]);
        pw[c] = *reinterpret_cast<const float4*>(W + (size_t)(col0 + lr[c]) * ldw + lc[c]);
    }

    for (int k0 = 0; k0 < K; k0 += 64) {
#pragma unroll
        for (int c = 0; c < 4; c++) {
            float4 va = pa[c], vw = pw[c];
            *reinterpret_cast<float4*>(&As[lr[c]][lc[c]]) =
                make_float4(f2tf32(va.x), f2tf32(va.y), f2tf32(va.z), f2tf32(va.w));
            *reinterpret_cast<float4*>(&Ws[lr[c]][lc[c]]) =
                make_float4(f2tf32(vw.x), f2tf32(vw.y), f2tf32(vw.z), f2tf32(vw.w));
        }
        __syncthreads();

        int kn = k0 + 64;
        if (kn < K) {
#pragma unroll
            for (int c = 0; c < 4; c++) {
                pa[c] = *reinterpret_cast<const float4*>(
                    A + (size_t)(row0 + lr[c]) * lda + kn + lc[c]);
                pw[c] = *reinterpret_cast<const float4*>(
                    W + (size_t)(col0 + lr[c]) * ldw + kn + lc[c]);
            }
        }

#pragma unroll
        for (int ks = 0; ks < 8; ks++) {
            const int kk = ks << 3;
            uint32_t af[2][4], bf[2][2];
#pragma unroll
            for (int mi = 0; mi < 2; mi++) {
                int r = wm + (mi << 4) + g;
                af[mi][0] = fu(As[r][kk + tg]);
                af[mi][1] = fu(As[r + 8][kk + tg]);
                af[mi][2] = fu(As[r][kk + tg + 4]);
                af[mi][3] = fu(As[r + 8][kk + tg + 4]);
            }
#pragma unroll
            for (int ni = 0; ni < 2; ni++) {
                int cn = wn + (ni << 3) + g;
                bf[ni][0] = fu(Ws[cn][kk + tg]);
                bf[ni][1] = fu(Ws[cn][kk + tg + 4]);
            }
#pragma unroll
            for (int mi = 0; mi < 2; mi++)
#pragma unroll
                for (int ni = 0; ni < 2; ni++)
                    mma_tf32(acc[mi][ni], af[mi], bf[ni]);
        }
        __syncthreads();
    }

#pragma unroll
    for (int mi = 0; mi < 2; mi++) {
#pragma unroll
        for (int ni = 0; ni < 2; ni++) {
            int col = col0 + wn + (ni << 3) + (tg << 1);
            float b0 = 0.f, b1 = 0.f;
            if (BIAS) { b0 = bias[col]; b1 = bias[col + 1]; }
            int r0 = row0 + wm + (mi << 4) + g;
            int r1 = r0 + 8;
            *reinterpret_cast<float2*>(C + (size_t)r0 * ldc + col) =
                make_float2(acc[mi][ni][0] + b0, acc[mi][ni][1] + b1);
            *reinterpret_cast<float2*>(C + (size_t)r1 * ldc + col) =
                make_float2(acc[mi][ni][2] + b0, acc[mi][ni][3] + b1);
        }
    }
}

// ---------------------------------------------------------------------------
// K1: qproj + kproj. 256 blocks x 256 thr, 64x64 tiles, BK=64.
// ---------------------------------------------------------------------------
__global__ void __launch_bounds__(256) k1_proj(
    const float* __restrict__ query, const float* __restrict__ memory,
    const float* __restrict__ Wq, const float* __restrict__ bq,
    const float* __restrict__ Wk, const float* __restrict__ bk)
{
    __shared__ float As[64][68];
    __shared__ float Ws[64][68];
    const int t = blockIdx.x & 127;
    const int row0 = (t >> 3) << 6;
    const int col0 = (t & 7) << 6;
    if (blockIdx.x < 128)
        gemm_nt_bk64<true>(As, Ws, row0, col0, query, DQS, Wq, DQS, bq,
                           g_qproj, HH, DQS);
    else
        gemm_nt_bk64<true>(As, Ws, row0, col0, memory, DKS, Wk, DKS, bk,
                           g_kproj, HH, DKS);
}

// ---------------------------------------------------------------------------
// NT tf32 GEMM body 64x64, BK=32 (round-6 exact) — k2's fused blocks.
// ---------------------------------------------------------------------------
template<bool BIAS>
__device__ __forceinline__ void gemm_nt_256(
    float (*As)[36], float (*Ws)[36],
    int row0, int col0,
    const float* __restrict__ A, int lda,
    const float* __restrict__ W, int ldw,
    const float* __restrict__ bias,
    float* __restrict__ C, int ldc, int K)
{
    const int tid  = threadIdx.x;
    const int lane = tid & 31;
    const int g    = lane >> 2;
    const int tg   = lane & 3;
    const int w    = tid >> 5;
    const int wm   = (w >> 2) << 5;
    const int wn   = (w & 3) << 4;

    int lr[2], lc[2];
#pragma unroll
    for (int c = 0; c < 2; c++) {
        int idx = tid + (c << 8);
        lr[c] = idx >> 3;
        lc[c] = (idx & 7) << 2;
    }

    float acc[2][2][4];
#pragma unroll
    for (int mi = 0; mi < 2; mi++)
#pragma unroll
        for (int ni = 0; ni < 2; ni++)
#pragma unroll
            for (int j = 0; j < 4; j++) acc[mi][ni][j] = 0.f;

    float4 pa[2], pw[2];
#pragma unroll
    for (int c = 0; c < 2; c++) {
        pa[c] = *reinterpret_cast<const float4*>(A + (size_t)(row0 + lr[c]) * lda + lc[c]);
        pw[c] = *reinterpret_cast<const float4*>(W + (size_t)(col0 + lr[c]) * ldw + lc[c]);
    }

    for (int k0 = 0; k0 < K; k0 += 32) {
#pragma unroll
        for (int c = 0; c < 2; c++) {
            float4 va = pa[c], vw = pw[c];
            *reinterpret_cast<float4*>(&As[lr[c]][lc[c]]) =
                make_float4(f2tf32(va.x), f2tf32(va.y), f2tf32(va.z), f2tf32(va.w));
            *reinterpret_cast<float4*>(&Ws[lr[c]][lc[c]]) =
                make_float4(f2tf32(vw.x), f2tf32(vw.y), f2tf32(vw.z), f2tf32(vw.w));
        }
        __syncthreads();

        int kn = k0 + 32;
        if (kn < K) {
#pragma unroll
            for (int c = 0; c < 2; c++) {
                pa[c] = *reinterpret_cast<const float4*>(
                    A + (size_t)(row0 + lr[c]) * lda + kn + lc[c]);
                pw[c] = *reinterpret_cast<const float4*>(
                    W + (size_t)(col0 + lr[c]) * ldw + kn + lc[c]);
            }
        }

#pragma unroll
        for (int ks = 0; ks < 4; ks++) {
            const int kk = ks << 3;
            uint32_t af[2][4], bf[2][2];
#pragma unroll
            for (int mi = 0; mi < 2; mi++) {
                int r = wm + (mi << 4) + g;
                af[mi][0] = fu(As[r][kk + tg]);
                af[mi][1] = fu(As[r + 8][kk + tg]);
                af[mi][2] = fu(As[r][kk + tg + 4]);
                af[mi][3] = fu(As[r + 8][kk + tg + 4]);
            }
#pragma unroll
            for (int ni = 0; ni < 2; ni++) {
                int cn = wn + (ni << 3) + g;
                bf[ni][0] = fu(Ws[cn][kk + tg]);
                bf[ni][1] = fu(Ws[cn][kk + tg + 4]);
            }
#pragma unroll
            for (int mi = 0; mi < 2; mi++)
#pragma unroll
                for (int ni = 0; ni < 2; ni++)
                    mma_tf32(acc[mi][ni], af[mi], bf[ni]);
        }
        __syncthreads();
    }

#pragma unroll
    for (int mi = 0; mi < 2; mi++) {
#pragma unroll
        for (int ni = 0; ni < 2; ni++) {
            int col = col0 + wn + (ni << 3) + (tg << 1);
            float b0 = 0.f, b1 = 0.f;
            if (BIAS) { b0 = bias[col]; b1 = bias[col + 1]; }
            int r0 = row0 + wm + (mi << 4) + g;
            int r1 = r0 + 8;
            *reinterpret_cast<float2*>(C + (size_t)r0 * ldc + col) =
                make_float2(acc[mi][ni][0] + b0, acc[mi][ni][1] + b1);
            *reinterpret_cast<float2*>(C + (size_t)r1 * ldc + col) =
                make_float2(acc[mi][ni][2] + b0, acc[mi][ni][3] + b1);
        }
    }
}

// ---------------------------------------------------------------------------
// Scores body (round-6 exact: f32 tanh.approx, raw logits; k3 masks).
// ---------------------------------------------------------------------------
__device__ __forceinline__ void scores_body(int bid, float (*ks)[512],
                                            const float* __restrict__ Wl)
{
    const int b  = bid >> 7;
    const int qg = (bid >> 2) & 31;
    const int mg = bid & 3;
    const int q0 = qg << 3;
    const int m0base = mg << 6;

    const int tid = threadIdx.x;
    const int lane = tid & 31;
    const int w = tid >> 5;
    const int q = q0 + w;

    float qr[16], wl[16];
    const float* qp = g_qproj + ((size_t)(b * QQ + q)) * HH;
#pragma unroll
    for (int j = 0; j < 16; j++) {
        qr[j] = qp[lane + 32 * j];
        wl[j] = Wl[lane + 32 * j];
    }

    float* lout = g_logits + ((size_t)(b * QQ + q)) * MMM;

    for (int t = 0; t < 4; t++) {
        const int m0 = m0base + (t << 4);
        __syncthreads();
        const float* kp = g_kproj + ((size_t)(b * MMM + m0)) * HH;
#pragma unroll
        for (int i = 0; i < 8; i++) {
            int idx = tid + (i << 8);
            int mm = idx >> 7;
            int c4 = (idx & 127) << 2;
            *reinterpret_cast<float4*>(&ks[mm][c4]) =
                *reinterpret_cast<const float4*>(kp + mm * HH + c4);
        }
        __syncthreads();

#pragma unroll 4
        for (int mm = 0; mm < 16; mm++) {
            float acc = 0.f;
#pragma unroll
            for (int j = 0; j < 16; j++) {
                float s = qr[j] + ks[mm][lane + 32 * j];
                float th;
                asm("tanh.approx.f32 %0, %1;" : "=f"(th) : "f"(s));
                acc = fmaf(wl[j], th, acc);
            }
#pragma unroll
            for (int o = 16; o > 0; o >>= 1)
                acc += __shfl_xor_sync(0xFFFFFFFFu, acc, o);
            if (lane == 0) lout[m0 + mm] = acc;
        }
    }
}

// ---------------------------------------------------------------------------
// K2: scores (512) + partial=query@Wo1^T+bo (128) + P2=memory@Wo2^T (128).
// (round-6 exact)
// ---------------------------------------------------------------------------
__global__ void __launch_bounds__(256) k2_scores_fused(
    const float* __restrict__ query, const float* __restrict__ memory,
    const float* __restrict__ Wo, const float* __restrict__ bo,
    const float* __restrict__ Wl)
{
    __shared__ __align__(16) union {
        float ks[16][512];                                 // 32 KB
        struct { float As[64][36]; float Ws[64][36]; } g;  // 18 KB
    } sm;

    const int bid = blockIdx.x;
    if (bid < 512) {
        scores_body(bid, sm.ks, Wl);
    } else if (bid < 640) {
        const int t = bid - 512;
        gemm_nt_256<true>(sm.g.As, sm.g.Ws, (t >> 3) << 6, (t & 7) << 6,
                          query, DQS, Wo, DC, bo, g_partial, DQS, DQS);
    } else {
        const int t = bid - 640;
        gemm_nt_256<false>(sm.g.As, sm.g.Ws, (t >> 3) << 6, (t & 7) << 6,
                           memory, DKS, Wo + DQS, DC, nullptr, g_P2, DQS, DKS);
    }
}

// ---------------------------------------------------------------------------
// K3: softmax + mask (round-6 exact). 256 blocks x 128 threads.
// ---------------------------------------------------------------------------
__global__ void __launch_bounds__(128) k3_softmax(
    const unsigned int* __restrict__ mask,
    float* __restrict__ weights)
{
    const int bid = blockIdx.x;
    const int b = bid >> 6;
    const int lane = threadIdx.x & 31;
    const int w = threadIdx.x >> 5;
    const int q = ((bid & 63) << 2) + w;

    const float* lin = g_logits + ((size_t)(b * QQ + q)) * MMM;
    const unsigned int* mrow = mask + b * MMM;

    float v[8];
    float mx = -3.4e38f;
#pragma unroll
    for (int j = 0; j < 8; j++) {
        int m = lane + 32 * j;
        float s = lin[m];
        if (mrow[m] != 0u) s = -1e18f;
        v[j] = s;
        mx = fmaxf(mx, s);
    }
#pragma unroll
    for (int o = 16; o > 0; o >>= 1)
        mx = fmaxf(mx, __shfl_xor_sync(0xFFFFFFFFu, mx, o));
    float sum = 0.f;
#pragma unroll
    for (int j = 0; j < 8; j++) {
        v[j] = __expf(v[j] - mx);
        sum += v[j];
    }
#pragma unroll
    for (int o = 16; o > 0; o >>= 1)
        sum += __shfl_xor_sync(0xFFFFFFFFu, sum, o);
    float inv = 1.f / sum;

    float* wout = weights + ((size_t)(b * QQ + q)) * MMM;
#pragma unroll
    for (int j = 0; j < 8; j++)
        wout[lane + 32 * j] = v[j] * inv;
}

// ---------------------------------------------------------------------------
// K4: out = tanh(partial + weights @ P2)  (batched NN, K = 256).
// Round-15 measured-best shape: 32x64 tiles, 256 threads (warp tile 16x16),
// grid 256 blocks. Measured 11.94us, occ 21.6%.
// ---------------------------------------------------------------------------
__global__ void __launch_bounds__(256) k4_final(
    const float* __restrict__ Wt, float* __restrict__ out)
{
    const int bid = blockIdx.x;
    const int b  = bid >> 6;
    const int t  = bid & 63;
    const int row0 = (t >> 3) << 5;   // 32-row q tile
    const int col0 = (t & 7) << 6;    // 64-col o tile

    const float* A  = Wt   + (size_t)b * QQ * MMM;   // weights, lda = MMM
    const float* Bm = g_P2 + (size_t)b * MMM * DQS;  // P2, ldb = DQS

    __shared__ float As[32][36];
    __shared__ float Bs[32][72];

    const int tid  = threadIdx.x;
    const int lane = tid & 31;
    const int g    = lane >> 2;
    const int tg   = lane & 3;
    const int w    = tid >> 5;
    const int wm   = (w >> 2) << 4;   // 0 or 16
    const int wn   = (w & 3) << 4;    // 0,16,32,48

    const int ar = tid >> 3, ac = (tid & 7) << 2;
    int br[2], bc[2];
#pragma unroll
    for (int c = 0; c < 2; c++) {
        int idx = tid + (c << 8);
        br[c] = idx >> 4;
        bc[c] = (idx & 15) << 2;
    }

    float acc[2][4];
#pragma unroll
    for (int ni = 0; ni < 2; ni++)
#pragma unroll
        for (int j = 0; j < 4; j++) acc[ni][j] = 0.f;

    float4 pa, pb[2];
    pa = *reinterpret_cast<const float4*>(A + (size_t)(row0 + ar) * MMM + ac);
#pragma unroll
    for (int c = 0; c < 2; c++)
        pb[c] = *reinterpret_cast<const float4*>(Bm + (size_t)br[c] * DQS + col0 + bc[c]);

    for (int k0 = 0; k0 < MMM; k0 += 32) {
        {
            float4 va = pa;
            *reinterpret_cast<float4*>(&As[ar][ac]) =
                make_float4(f2tf32(va.x), f2tf32(va.y), f2tf32(va.z), f2tf32(va.w));
        }
#pragma unroll
        for (int c = 0; c < 2; c++) {
            float4 vb = pb[c];
            *reinterpret_cast<float4*>(&Bs[br[c]][bc[c]]) =
                make_float4(f2tf32(vb.x), f2tf32(vb.y), f2tf32(vb.z), f2tf32(vb.w));
        }
        __syncthreads();

        int kn = k0 + 32;
        if (kn < MMM) {
            pa = *reinterpret_cast<const float4*>(A + (size_t)(row0 + ar) * MMM + kn + ac);
#pragma unroll
            for (int c = 0; c < 2; c++)
                pb[c] = *reinterpret_cast<const float4*>(
                    Bm + (size_t)(kn + br[c]) * DQS + col0 + bc[c]);
        }

#pragma unroll
        for (int ks = 0; ks < 4; ks++) {
            const int kk = ks << 3;
            uint32_t af[4], bf[2][2];
            {
                int r = wm + g;
                af[0] = fu(As[r][kk + tg]);
                af[1] = fu(As[r + 8][kk + tg]);
                af[2] = fu(As[r][kk + tg + 4]);
                af[3] = fu(As[r + 8][kk + tg + 4]);
            }
#pragma unroll
            for (int ni = 0; ni < 2; ni++) {
                int cn = wn + (ni << 3) + g;
                bf[ni][0] = fu(Bs[kk + tg][cn]);
                bf[ni][1] = fu(Bs[kk + tg + 4][cn]);
            }
#pragma unroll
            for (int ni = 0; ni < 2; ni++)
                mma_tf32(acc[ni], af, bf[ni]);
        }
        __syncthreads();
    }

#pragma unroll
    for (int ni = 0; ni < 2; ni++) {
        int col = col0 + wn + (ni << 3) + (tg << 1);
        size_t r0 = (size_t)b * QQ + row0 + wm + g;
        size_t r1 = r0 + 8;
        float2 p0 = *reinterpret_cast<const float2*>(&g_partial[r0 * DQS + col]);
        float2 p1 = *reinterpret_cast<const float2*>(&g_partial[r1 * DQS + col]);
        *reinterpret_cast<float2*>(out + r0 * DQS + col) =
            make_float2(tanhf(acc[ni][0] + p0.x), tanhf(acc[ni][1] + p0.y));
        *reinterpret_cast<float2*>(out + r1 * DQS + col) =
            make_float2(tanhf(acc[ni][2] + p1.x), tanhf(acc[ni][3] + p1.y));
    }
}

// ---------------------------------------------------------------------------
// Launch
// ---------------------------------------------------------------------------
extern "C" void kernel_launch(void* const* d_in, const int* in_sizes, int n_in,
                              void* d_out, int out_size)
{
    const float* query  = (const float*)d_in[0];
    const float* memory = (const float*)d_in[1];
    const unsigned int* mask = (const unsigned int*)d_in[2];
    const float* Wk = (const float*)d_in[3];
    const float* bk = (const float*)d_in[4];
    const float* Wq = (const float*)d_in[5];
    const float* bq = (const float*)d_in[6];
    const float* Wl = (const float*)d_in[7];
    // d_in[8] = bl (uniform shift — cancels in softmax)
    const float* Wo = (const float*)d_in[9];
    const float* bo = (const float*)d_in[10];

    float* out     = (float*)d_out;
    float* weights = out + BB * QQ * DQS;

    k1_proj<<<256, 256>>>(query, memory, Wq, bq, Wk, bk);
    k2_scores_fused<<<768, 256>>>(query, memory, Wo, bo, Wl);
    k3_softmax<<<256, 128>>>(mask, weights);
    k4_final<<<256, 256>>>(weights, out);
}